// round 15
// baseline (speedup 1.0000x reference)
#include <cuda_runtime.h>

#define DINL __device__ __forceinline__

namespace {
constexpr int Bn = 32, Sn = 256, En = 256, Hn = 512, Ln = 1024;
constexpr int NBLK = 256, NTHR = 256;
constexpr int NCH = 8;              // attention chunks per batch row
constexpr int CROWS = Ln / NCH;     // 128 L-rows per chunk
}

__device__ float g_he[Bn * Ln * Hn];     // projected encoder (64 MB)
__device__ float g_hbuf[2][Bn * Hn];
__device__ float g_c[Bn * Hn];
__device__ float g_att[Bn * Hn];
__device__ float g_se[Bn * Hn];
__device__ float g_pm[NBLK], g_ps[NBLK];
__device__ float g_pctx[NBLK * Hn];
__device__ volatile unsigned g_gen;
__device__ unsigned g_cnt;

struct SC {
    float se[Hn];
    float hb[Hn];
    float wgt[CROWS];
    float esc[CROWS];
    float redm[8], reds[8];
};
union __align__(16) SmemU {
    float xs[32][132];   // x staging [b][k]; 132 floats = 33 x 16B chunks (LDS.128 conflict-free)
    float es[32][132];   // precompute enc staging
    SC c;
};

DINL void gsync() {
    __threadfence();
    __syncthreads();
    if (threadIdx.x == 0) {
        unsigned target = g_gen + 1u;
        if (atomicAdd(&g_cnt, 1u) == gridDim.x - 1u) {
            g_cnt = 0u;
            __threadfence();
            g_gen = target;
        } else {
            while (g_gen != target) { }
            __threadfence();
        }
    }
    __syncthreads();
}

DINL float wredsum(float v) {
    v += __shfl_xor_sync(0xffffffffu, v, 16);
    v += __shfl_xor_sync(0xffffffffu, v, 8);
    v += __shfl_xor_sync(0xffffffffu, v, 4);
    v += __shfl_xor_sync(0xffffffffu, v, 2);
    v += __shfl_xor_sync(0xffffffffu, v, 1);
    return v;
}

DINL float sigm(float x) { return 1.0f / (1.0f + __expf(-x)); }

DINL void ffma2(unsigned long long& acc, unsigned long long a, unsigned long long b) {
    asm("fma.rn.f32x2 %0, %1, %2, %0;" : "+l"(acc) : "l"(a), "l"(b));
}
DINL unsigned long long packf2(float a, float b) {
    unsigned long long r;
    asm("mov.b64 %0, {%1, %2};" : "=l"(r) : "f"(a), "f"(b));
    return r;
}
DINL float lo2(unsigned long long v) { return __uint_as_float((unsigned)v); }
DINL float hi2(unsigned long long v) { return __uint_as_float((unsigned)(v >> 32)); }

__global__ void __launch_bounds__(NTHR, 2) aas_kernel(
    const float* __restrict__ y,    const float* __restrict__ enc,
    const float* __restrict__ W_ih, const float* __restrict__ b_ih,
    const float* __restrict__ W_hh, const float* __restrict__ b_hh,
    const float* __restrict__ W_s,  const float* __restrict__ b_s,
    const float* __restrict__ W_h,  const float* __restrict__ b_h,
    float* __restrict__ outp)
{
    __shared__ SmemU smu;
    __shared__ float sm_g[8][32];

    const int tid  = threadIdx.x;
    const int lane = tid & 31;
    const int w    = tid >> 5;
    const int bid  = blockIdx.x;
    const int gtid = bid * NTHR + tid;

    // ---------------- init state ----------------
    for (int i = gtid; i < Bn * Hn; i += NBLK * NTHR) {
        g_hbuf[0][i] = 0.f; g_hbuf[1][i] = 0.f; g_c[i] = 0.f;
        __stcg(&g_att[i], 0.f);
    }

    // ---------------- precompute h_e = enc @ W_h^T + b_h ----------------
    // row-groups of 32 rows; warp w owns output cols [w*64, w*64+64), in 4 sub-passes of 16
    for (int rg = bid; rg < (Bn * Ln) / 32; rg += NBLK) {
        for (int sub = 0; sub < 4; sub++) {
            const int kb = w * 64 + sub * 16;
            unsigned long long acc[16];
#pragma unroll
            for (int kk = 0; kk < 16; kk++) acc[kk] = 0ull;
            for (int ch = 0; ch < 4; ch++) {
                __syncthreads();
                {   // stage enc rows [rg*32..+32), h in [ch*128..+128)
                    const int bb = tid & 31, kg = tid >> 5;
                    const float* src = enc + (rg * 32 + bb) * Hn + ch * 128 + kg * 16;
#pragma unroll
                    for (int i = 0; i < 4; i++)
                        *(float4*)&smu.es[bb][kg * 16 + i * 4] = *(const float4*)(src + i * 4);
                }
                __syncthreads();
#pragma unroll 4
                for (int h4 = 0; h4 < 128; h4 += 4) {
                    const ulonglong2 xv = *(const ulonglong2*)&smu.es[lane][h4];
                    const float* wp = W_h + ch * 128 + h4;
#pragma unroll
                    for (int kk = 0; kk < 16; kk++) {
                        const ulonglong2 wv = *(const ulonglong2*)(wp + (kb + kk) * Hn);
                        ffma2(acc[kk], wv.x, xv.x);
                        ffma2(acc[kk], wv.y, xv.y);
                    }
                }
            }
            float* dst = g_he + (rg * 32 + lane) * Hn + kb;
#pragma unroll
            for (int kk = 0; kk < 16; kk++)
                dst[kk] = lo2(acc[kk]) + hi2(acc[kk]) + b_h[kb + kk];
        }
    }
    gsync();

    // ==================== time-step loop ====================
#pragma unroll 1
    for (int ts = 0; ts < Sn; ts++) {
        const int cur = ts & 1, nxt = cur ^ 1;

        // ---------- A: gates GEMM (prefetch-pipelined, FFMA2) + LSTM cell ----------
        {
            const int q = w & 3, j = w >> 2;
            const int r = q * Hn + bid * 2 + j;      // gate row
            unsigned long long a01 = 0ull, a23 = 0ull;
            const int sb = tid & 31, kg = tid >> 5;
            float4 pf[4];

            auto ldx = [&](int ch) {
                const float* src;
                bool cg;
                if (ch < 2)      { src = y + (sb * Sn + ts) * En + ch * 128;      cg = false; }
                else if (ch < 6) { src = g_att + sb * Hn + (ch - 2) * 128;        cg = true;  }
                else             { src = g_hbuf[cur] + sb * Hn + (ch - 6) * 128;  cg = true;  }
                src += kg * 16;
#pragma unroll
                for (int i = 0; i < 4; i++)
                    pf[i] = cg ? __ldcg((const float4*)(src + i * 4))
                               : *(const float4*)(src + i * 4);
            };

            ldx(0);
#pragma unroll 1
            for (int ch = 0; ch < 10; ch++) {
                __syncthreads();
#pragma unroll
                for (int i = 0; i < 4; i++)
                    *(float4*)&smu.xs[sb][kg * 16 + i * 4] = pf[i];
                __syncthreads();
                if (ch < 9) ldx(ch + 1);

                const float* wp = (ch < 6) ? W_ih + r * 768 + ch * 128
                                           : W_hh + r * Hn + (ch - 6) * 128;
#pragma unroll 8
                for (int g4 = 0; g4 < 32; g4++) {
                    const int k = g4 * 4;
                    const ulonglong2 wv = *(const ulonglong2*)(wp + k);
                    const ulonglong2 xv = *(const ulonglong2*)&smu.xs[lane][k];
                    ffma2(a01, wv.x, xv.x);
                    ffma2(a23, wv.y, xv.y);
                }
            }
            sm_g[w][lane] = lo2(a01) + hi2(a01) + lo2(a23) + hi2(a23)
                          + b_ih[r] + b_hh[r];
            __syncthreads();
            if (tid < 64) {
                const int bb = tid & 31, jj = tid >> 5, u = bid * 2 + jj;
                const float ig = sigm(sm_g[jj * 4 + 0][bb]);
                const float fg = sigm(sm_g[jj * 4 + 1][bb]);
                const float gg = tanhf(sm_g[jj * 4 + 2][bb]);
                const float og = sigm(sm_g[jj * 4 + 3][bb]);
                const float c = fmaf(fg, g_c[bb * Hn + u], ig * gg);
                g_c[bb * Hn + u] = c;
                const float h = og * tanhf(c);
                __stcg(&g_hbuf[nxt][bb * Hn + u], h);
                outp[(bb * Sn + ts) * Hn + u] = h;
            }
        }
        gsync();

        // ---------- B: partitioned s_e = W_s h + b_s (64 outputs per block) ----------
        {
            const int b = bid >> 3, mb = (bid & 7) * 64;
            if (tid < 128)
                *(float4*)&smu.c.hb[tid * 4] =
                    __ldcg((const float4*)(g_hbuf[nxt] + b * Hn + tid * 4));
            __syncthreads();
            const int m = mb + w * 8 + (lane >> 2);
            const int qd = lane & 3;
            const float* wsp = W_s + m * Hn + qd * 128;
            unsigned long long a0 = 0ull, a1 = 0ull;
#pragma unroll 8
            for (int i = 0; i < 32; i++) {
                const ulonglong2 wv = *(const ulonglong2*)(wsp + i * 4);
                const ulonglong2 xv = *(const ulonglong2*)&smu.c.hb[qd * 128 + i * 4];
                ffma2(a0, wv.x, xv.x);
                ffma2(a1, wv.y, xv.y);
            }
            float v = lo2(a0) + hi2(a0) + lo2(a1) + hi2(a1);
            v += __shfl_xor_sync(0xffffffffu, v, 1);
            v += __shfl_xor_sync(0xffffffffu, v, 2);
            if (qd == 0) __stcg(&g_se[b * Hn + m], v + b_s[m]);
        }
        gsync();

        // ---------- C: two-pass softmax attention over 128 L-rows ----------
        {
            const int b = bid >> 3, chunk = bid & 7;
            if (tid < 128)
                *(float4*)&smu.c.se[tid * 4] =
                    __ldcg((const float4*)(g_se + b * Hn + tid * 4));
            __syncthreads();

            // pass 1: lane-per-row scores (rl = lane&15, two h-halves across half-warps)
            {
                const int rl = lane & 15, hh = lane >> 4;
                const int row = chunk * CROWS + w * 16 + rl;
                const float* hp = g_he + (b * Ln + row) * Hn + hh * 256;
                const float* sp = smu.c.se + hh * 256;
                unsigned long long ea = 0ull, eb = 0ull;
#pragma unroll 8
                for (int i = 0; i < 64; i++) {
                    const ulonglong2 hv = *(const ulonglong2*)(hp + i * 4);
                    const ulonglong2 sv = *(const ulonglong2*)(sp + i * 4);
                    ffma2(ea, hv.x, sv.x);
                    ffma2(eb, hv.y, sv.y);
                }
                float e = lo2(ea) + hi2(ea) + lo2(eb) + hi2(eb);
                e += __shfl_xor_sync(0xffffffffu, e, 16);
                if (hh == 0) smu.c.esc[w * 16 + rl] = e;
                float mx = e;
                mx = fmaxf(mx, __shfl_xor_sync(0xffffffffu, mx, 8));
                mx = fmaxf(mx, __shfl_xor_sync(0xffffffffu, mx, 4));
                mx = fmaxf(mx, __shfl_xor_sync(0xffffffffu, mx, 2));
                mx = fmaxf(mx, __shfl_xor_sync(0xffffffffu, mx, 1));
                if (lane == 0) smu.c.redm[w] = mx;
            }
            __syncthreads();
            {
                float M = smu.c.redm[0];
#pragma unroll
                for (int w2 = 1; w2 < 8; w2++) M = fmaxf(M, smu.c.redm[w2]);
                if (tid < CROWS) {
                    const float wg = __expf(smu.c.esc[tid] - M);
                    smu.c.wgt[tid] = wg;
                    const float s = wredsum(wg);
                    if (lane == 0) smu.c.reds[w] = s;
                }
                __syncthreads();
                if (tid == 0) {
                    const float Sb = smu.c.reds[0] + smu.c.reds[1]
                                   + smu.c.reds[2] + smu.c.reds[3];
                    __stcg(&g_pm[bid], M);
                    __stcg(&g_ps[bid], Sb);
                }
            }

            // pass 2: ctx[h] = sum_l wgt[l] * he[l][h]; lane owns 2 h
            {
                const int h0 = w * 64 + lane * 2;
                const float* hc = g_he + (b * Ln + chunk * CROWS) * Hn + h0;
                unsigned long long a0 = 0ull, a1 = 0ull, a2 = 0ull, a3 = 0ull;
#pragma unroll 2
                for (int li = 0; li < CROWS; li += 4) {
                    ffma2(a0, *(const unsigned long long*)(hc + (li + 0) * Hn),
                          packf2(smu.c.wgt[li],     smu.c.wgt[li]));
                    ffma2(a1, *(const unsigned long long*)(hc + (li + 1) * Hn),
                          packf2(smu.c.wgt[li + 1], smu.c.wgt[li + 1]));
                    ffma2(a2, *(const unsigned long long*)(hc + (li + 2) * Hn),
                          packf2(smu.c.wgt[li + 2], smu.c.wgt[li + 2]));
                    ffma2(a3, *(const unsigned long long*)(hc + (li + 3) * Hn),
                          packf2(smu.c.wgt[li + 3], smu.c.wgt[li + 3]));
                }
                const float cx = (lo2(a0) + lo2(a1)) + (lo2(a2) + lo2(a3));
                const float cy = (hi2(a0) + hi2(a1)) + (hi2(a2) + hi2(a3));
                __stcg((float2*)(g_pctx + bid * Hn + h0), make_float2(cx, cy));
            }
        }
        gsync();

        // ---------- D: combine 8 chunk-partials -> att ----------
        if (gtid < Bn * Hn) {
            const int b = gtid >> 9, h = gtid & 511;
            float pm[8];
#pragma unroll
            for (int cc = 0; cc < 8; cc++) pm[cc] = __ldcg(&g_pm[b * 8 + cc]);
            float M = pm[0];
#pragma unroll
            for (int cc = 1; cc < 8; cc++) M = fmaxf(M, pm[cc]);
            float Sd = 0.f, v = 0.f;
#pragma unroll
            for (int cc = 0; cc < 8; cc++) {
                const float wsc = __expf(pm[cc] - M);
                Sd = fmaf(wsc, __ldcg(&g_ps[b * 8 + cc]), Sd);
                v  = fmaf(wsc, __ldcg(&g_pctx[(b * 8 + cc) * Hn + h]), v);
            }
            const float a = v / Sd;
            __stcg(&g_att[b * Hn + h], a);
            outp[Bn * Sn * Hn + (b * Sn + ts) * Hn + h] = a;
        }
        gsync();
    }
}

extern "C" void kernel_launch(void* const* d_in, const int* in_sizes, int n_in,
                              void* d_out, int out_size) {
    (void)in_sizes; (void)n_in; (void)out_size;
    aas_kernel<<<NBLK, NTHR>>>(
        (const float*)d_in[0], (const float*)d_in[1],
        (const float*)d_in[2], (const float*)d_in[3],
        (const float*)d_in[4], (const float*)d_in[5],
        (const float*)d_in[6], (const float*)d_in[7],
        (const float*)d_in[8], (const float*)d_in[9],
        (float*)d_out);
}

// round 16
// speedup vs baseline: 1.6003x; 1.6003x over previous
#include <cuda_runtime.h>

#define DINL __device__ __forceinline__

namespace {
constexpr int Bn = 32, Sn = 256, En = 256, Hn = 512, Ln = 1024;
constexpr int NBLK = 256, NTHR = 256;
constexpr int NCH = 8;              // attention chunks per batch row
constexpr int CROWS = Ln / NCH;     // 128 L-rows per chunk
}

__device__ float g_he[Bn * Ln * Hn];     // projected encoder (64 MB)
__device__ float g_hbuf[2][Bn * Hn];
__device__ float g_c[Bn * Hn];
__device__ float g_att[Bn * Hn];
__device__ float g_se[Bn * Hn];
__device__ float g_pm[NBLK], g_ps[NBLK];
__device__ float g_pctx[NBLK * Hn];
__device__ volatile unsigned g_gen;
__device__ unsigned g_cnt;

struct SC {
    float se[Hn];
    float hb[Hn];
    float wgt[CROWS];
    float esc[CROWS];
    float redm[8], reds[8];
};
union __align__(16) SmemU {
    float xs[32][132];   // x staging [b][k]; stride 132 -> conflict-free LDS.128
    float es[32][132];   // precompute enc staging
    SC c;
};

DINL void gsync() {
    __threadfence();
    __syncthreads();
    if (threadIdx.x == 0) {
        unsigned target = g_gen + 1u;
        if (atomicAdd(&g_cnt, 1u) == gridDim.x - 1u) {
            g_cnt = 0u;
            __threadfence();
            g_gen = target;
        } else {
            while (g_gen != target) { __nanosleep(64); }
            __threadfence();
        }
    }
    __syncthreads();
}

DINL float wredsum(float v) {
    v += __shfl_xor_sync(0xffffffffu, v, 16);
    v += __shfl_xor_sync(0xffffffffu, v, 8);
    v += __shfl_xor_sync(0xffffffffu, v, 4);
    v += __shfl_xor_sync(0xffffffffu, v, 2);
    v += __shfl_xor_sync(0xffffffffu, v, 1);
    return v;
}

DINL float sigm(float x) { return 1.0f / (1.0f + __expf(-x)); }

DINL void ffma2(unsigned long long& acc, unsigned long long a, unsigned long long b) {
    asm("fma.rn.f32x2 %0, %1, %2, %0;" : "+l"(acc) : "l"(a), "l"(b));
}
DINL unsigned long long packf2(float a, float b) {
    unsigned long long r;
    asm("mov.b64 %0, {%1, %2};" : "=l"(r) : "f"(a), "f"(b));
    return r;
}
DINL float lo2(unsigned long long v) { return __uint_as_float((unsigned)v); }
DINL float hi2(unsigned long long v) { return __uint_as_float((unsigned)(v >> 32)); }
DINL float red2(unsigned long long v) { return lo2(v) + hi2(v); }

__global__ void __launch_bounds__(NTHR, 2) aas_kernel(
    const float* __restrict__ y,    const float* __restrict__ enc,
    const float* __restrict__ W_ih, const float* __restrict__ b_ih,
    const float* __restrict__ W_hh, const float* __restrict__ b_hh,
    const float* __restrict__ W_s,  const float* __restrict__ b_s,
    const float* __restrict__ W_h,  const float* __restrict__ b_h,
    float* __restrict__ outp)
{
    __shared__ SmemU smu;
    __shared__ float sm_g[8][32];

    const int tid  = threadIdx.x;
    const int lane = tid & 31;
    const int w    = tid >> 5;
    const int bid  = blockIdx.x;
    const int gtid = bid * NTHR + tid;

    // ---------------- init state ----------------
    for (int i = gtid; i < Bn * Hn; i += NBLK * NTHR) {
        g_hbuf[0][i] = 0.f; g_hbuf[1][i] = 0.f; g_c[i] = 0.f;
        __stcg(&g_att[i], 0.f);
    }

    // ---------------- precompute h_e = enc @ W_h^T + b_h ----------------
    // row-groups of 32 rows; warp w owns output cols [w*64, +64), 4 sub-passes of 16
    for (int rg = bid; rg < (Bn * Ln) / 32; rg += NBLK) {
        for (int sub = 0; sub < 4; sub++) {
            const int kb = w * 64 + sub * 16;
            unsigned long long acc[16];
#pragma unroll
            for (int kk = 0; kk < 16; kk++) acc[kk] = 0ull;
            for (int ch = 0; ch < 4; ch++) {
                __syncthreads();
                // coalesced stage: warp loads rows w*4..w*4+3, full 128-col chunk
#pragma unroll
                for (int rr = 0; rr < 4; rr++) {
                    const int bb = w * 4 + rr;
                    *(float4*)&smu.es[bb][lane * 4] =
                        *(const float4*)(enc + (rg * 32 + bb) * Hn + ch * 128 + lane * 4);
                }
                __syncthreads();
#pragma unroll 4
                for (int h4 = 0; h4 < 128; h4 += 4) {
                    const ulonglong2 xv = *(const ulonglong2*)&smu.es[lane][h4];
                    const float* wp = W_h + ch * 128 + h4;
#pragma unroll
                    for (int kk = 0; kk < 16; kk++) {
                        const ulonglong2 wv = *(const ulonglong2*)(wp + (kb + kk) * Hn);
                        ffma2(acc[kk], wv.x, xv.x);
                        ffma2(acc[kk], wv.y, xv.y);
                    }
                }
            }
            float* dst = g_he + (rg * 32 + lane) * Hn + kb;
#pragma unroll
            for (int kk = 0; kk < 16; kk++)
                dst[kk] = red2(acc[kk]) + b_h[kb + kk];
        }
    }
    gsync();

    // ==================== time-step loop ====================
#pragma unroll 1
    for (int ts = 0; ts < Sn; ts++) {
        const int cur = ts & 1, nxt = cur ^ 1;

        // ---------- A: gates GEMM (coalesced staging, FFMA2) + LSTM cell ----------
        {
            const int q = w & 3, j = w >> 2;
            const int r = q * Hn + bid * 2 + j;      // gate row
            unsigned long long a01 = 0ull, a23 = 0ull;
            float4 pf[4];

            auto ldx = [&](int ch) {
#pragma unroll
                for (int rr = 0; rr < 4; rr++) {
                    const int bb = w * 4 + rr;
                    if (ch < 2)
                        pf[rr] = *(const float4*)(y + (bb * Sn + ts) * En + ch * 128 + lane * 4);
                    else if (ch < 6)
                        pf[rr] = __ldcg((const float4*)(g_att + bb * Hn + (ch - 2) * 128 + lane * 4));
                    else
                        pf[rr] = __ldcg((const float4*)(g_hbuf[cur] + bb * Hn + (ch - 6) * 128 + lane * 4));
                }
            };

            ldx(0);
#pragma unroll 1
            for (int ch = 0; ch < 10; ch++) {
                __syncthreads();
#pragma unroll
                for (int rr = 0; rr < 4; rr++)
                    *(float4*)&smu.xs[w * 4 + rr][lane * 4] = pf[rr];
                __syncthreads();
                if (ch < 9) ldx(ch + 1);

                const float* wp = (ch < 6) ? W_ih + r * 768 + ch * 128
                                           : W_hh + r * Hn + (ch - 6) * 128;
#pragma unroll 8
                for (int g4 = 0; g4 < 32; g4++) {
                    const int k = g4 * 4;
                    const ulonglong2 wv = *(const ulonglong2*)(wp + k);
                    const ulonglong2 xv = *(const ulonglong2*)&smu.xs[lane][k];
                    ffma2(a01, wv.x, xv.x);
                    ffma2(a23, wv.y, xv.y);
                }
            }
            sm_g[w][lane] = red2(a01) + red2(a23) + b_ih[r] + b_hh[r];
            __syncthreads();
            if (tid < 64) {
                const int bb = tid & 31, jj = tid >> 5, u = bid * 2 + jj;
                const float ig = sigm(sm_g[jj * 4 + 0][bb]);
                const float fg = sigm(sm_g[jj * 4 + 1][bb]);
                const float gg = tanhf(sm_g[jj * 4 + 2][bb]);
                const float og = sigm(sm_g[jj * 4 + 3][bb]);
                const float c = fmaf(fg, g_c[bb * Hn + u], ig * gg);
                g_c[bb * Hn + u] = c;
                const float h = og * tanhf(c);
                __stcg(&g_hbuf[nxt][bb * Hn + u], h);
                outp[(bb * Sn + ts) * Hn + u] = h;
            }
        }
        gsync();

        // ---------- B: partitioned s_e = W_s h + b_s (coalesced, 64 outputs/block) ----------
        {
            const int b = bid >> 3, mb = (bid & 7) * 64;
            if (tid < 128)
                *(float4*)&smu.c.hb[tid * 4] =
                    __ldcg((const float4*)(g_hbuf[nxt] + b * Hn + tid * 4));
            __syncthreads();
#pragma unroll
            for (int rp = 0; rp < 4; rp++) {
                const int m0 = mb + w * 8 + rp * 2;
                unsigned long long a0 = 0ull, a1 = 0ull;
#pragma unroll
                for (int c = 0; c < 4; c++) {
                    const ulonglong2 xv = *(const ulonglong2*)&smu.c.hb[c * 128 + lane * 4];
                    const ulonglong2 w0 = *(const ulonglong2*)(W_s + m0 * Hn + c * 128 + lane * 4);
                    const ulonglong2 w1 = *(const ulonglong2*)(W_s + (m0 + 1) * Hn + c * 128 + lane * 4);
                    ffma2(a0, w0.x, xv.x); ffma2(a0, w0.y, xv.y);
                    ffma2(a1, w1.x, xv.x); ffma2(a1, w1.y, xv.y);
                }
                float e0 = wredsum(red2(a0));
                float e1 = wredsum(red2(a1));
                if (lane == 0) {
                    __stcg(&g_se[b * Hn + m0],     e0 + b_s[m0]);
                    __stcg(&g_se[b * Hn + m0 + 1], e1 + b_s[m0 + 1]);
                }
            }
        }
        gsync();

        // ---------- C: two-pass softmax attention over 128 L-rows ----------
        {
            const int b = bid >> 3, chunk = bid & 7;
            if (tid < 128)
                *(float4*)&smu.c.se[tid * 4] =
                    __ldcg((const float4*)(g_se + b * Hn + tid * 4));
            __syncthreads();

            // pass 1: coalesced scores, 4 rows concurrently per group
            {
                float emax = -1e30f;
#pragma unroll 1
                for (int rgp = 0; rgp < 4; rgp++) {
                    const int row0 = chunk * CROWS + w * 16 + rgp * 4;
                    const float* hp = g_he + (b * Ln + row0) * Hn + lane * 4;
                    unsigned long long a0 = 0ull, a1 = 0ull, a2 = 0ull, a3 = 0ull;
#pragma unroll
                    for (int c = 0; c < 4; c++) {
                        const ulonglong2 sv = *(const ulonglong2*)&smu.c.se[c * 128 + lane * 4];
                        const ulonglong2 h0 = *(const ulonglong2*)(hp + c * 128);
                        const ulonglong2 h1 = *(const ulonglong2*)(hp + Hn + c * 128);
                        const ulonglong2 h2 = *(const ulonglong2*)(hp + 2 * Hn + c * 128);
                        const ulonglong2 h3 = *(const ulonglong2*)(hp + 3 * Hn + c * 128);
                        ffma2(a0, h0.x, sv.x); ffma2(a0, h0.y, sv.y);
                        ffma2(a1, h1.x, sv.x); ffma2(a1, h1.y, sv.y);
                        ffma2(a2, h2.x, sv.x); ffma2(a2, h2.y, sv.y);
                        ffma2(a3, h3.x, sv.x); ffma2(a3, h3.y, sv.y);
                    }
                    const float e0 = wredsum(red2(a0));
                    const float e1 = wredsum(red2(a1));
                    const float e2 = wredsum(red2(a2));
                    const float e3 = wredsum(red2(a3));
                    emax = fmaxf(fmaxf(emax, fmaxf(e0, e1)), fmaxf(e2, e3));
                    if (lane == 0) {
                        smu.c.esc[w * 16 + rgp * 4 + 0] = e0;
                        smu.c.esc[w * 16 + rgp * 4 + 1] = e1;
                        smu.c.esc[w * 16 + rgp * 4 + 2] = e2;
                        smu.c.esc[w * 16 + rgp * 4 + 3] = e3;
                    }
                }
                if (lane == 0) smu.c.redm[w] = emax;
            }
            __syncthreads();
            {
                float M = smu.c.redm[0];
#pragma unroll
                for (int w2 = 1; w2 < 8; w2++) M = fmaxf(M, smu.c.redm[w2]);
                if (tid < CROWS) {
                    const float wg = __expf(smu.c.esc[tid] - M);
                    smu.c.wgt[tid] = wg;
                    const float s = wredsum(wg);
                    if (lane == 0) smu.c.reds[w] = s;
                }
                __syncthreads();
                if (tid == 0) {
                    const float Sb = smu.c.reds[0] + smu.c.reds[1]
                                   + smu.c.reds[2] + smu.c.reds[3];
                    __stcg(&g_pm[bid], M);
                    __stcg(&g_ps[bid], Sb);
                }
            }

            // pass 2: ctx[h] = sum_l wgt[l] * he[l][h]; lane owns 2 h (coalesced LDG.64)
            {
                const int h0 = w * 64 + lane * 2;
                const float* hc = g_he + (b * Ln + chunk * CROWS) * Hn + h0;
                unsigned long long a0 = 0ull, a1 = 0ull, a2 = 0ull, a3 = 0ull;
#pragma unroll 2
                for (int li = 0; li < CROWS; li += 4) {
                    ffma2(a0, *(const unsigned long long*)(hc + (li + 0) * Hn),
                          packf2(smu.c.wgt[li],     smu.c.wgt[li]));
                    ffma2(a1, *(const unsigned long long*)(hc + (li + 1) * Hn),
                          packf2(smu.c.wgt[li + 1], smu.c.wgt[li + 1]));
                    ffma2(a2, *(const unsigned long long*)(hc + (li + 2) * Hn),
                          packf2(smu.c.wgt[li + 2], smu.c.wgt[li + 2]));
                    ffma2(a3, *(const unsigned long long*)(hc + (li + 3) * Hn),
                          packf2(smu.c.wgt[li + 3], smu.c.wgt[li + 3]));
                }
                const float cx = (lo2(a0) + lo2(a1)) + (lo2(a2) + lo2(a3));
                const float cy = (hi2(a0) + hi2(a1)) + (hi2(a2) + hi2(a3));
                __stcg((float2*)(g_pctx + bid * Hn + h0), make_float2(cx, cy));
            }
        }
        gsync();

        // ---------- D: combine 8 chunk-partials -> att ----------
        if (gtid < Bn * Hn) {
            const int b = gtid >> 9, h = gtid & 511;
            float pm[8];
#pragma unroll
            for (int cc = 0; cc < 8; cc++) pm[cc] = __ldcg(&g_pm[b * 8 + cc]);
            float M = pm[0];
#pragma unroll
            for (int cc = 1; cc < 8; cc++) M = fmaxf(M, pm[cc]);
            float Sd = 0.f, v = 0.f;
#pragma unroll
            for (int cc = 0; cc < 8; cc++) {
                const float wsc = __expf(pm[cc] - M);
                Sd = fmaf(wsc, __ldcg(&g_ps[b * 8 + cc]), Sd);
                v  = fmaf(wsc, __ldcg(&g_pctx[(b * 8 + cc) * Hn + h]), v);
            }
            const float a = v / Sd;
            __stcg(&g_att[b * Hn + h], a);
            outp[Bn * Sn * Hn + (b * Sn + ts) * Hn + h] = a;
        }
        gsync();
    }
}

extern "C" void kernel_launch(void* const* d_in, const int* in_sizes, int n_in,
                              void* d_out, int out_size) {
    (void)in_sizes; (void)n_in; (void)out_size;
    aas_kernel<<<NBLK, NTHR>>>(
        (const float*)d_in[0], (const float*)d_in[1],
        (const float*)d_in[2], (const float*)d_in[3],
        (const float*)d_in[4], (const float*)d_in[5],
        (const float*)d_in[6], (const float*)d_in[7],
        (const float*)d_in[8], (const float*)d_in[9],
        (float*)d_out);
}

// round 17
// speedup vs baseline: 2.4597x; 1.5370x over previous
#include <cuda_runtime.h>

#define DINL __device__ __forceinline__

namespace {
constexpr int Bn = 32, Sn = 256, En = 256, Hn = 512, Ln = 1024;
constexpr int NBLK = 256, NTHR = 256;
constexpr int NCH = 8;              // attention chunks per batch row
constexpr int CROWS = Ln / NCH;     // 128 L-rows per chunk
}

__device__ float g_he[Bn * Ln * Hn];     // projected encoder (64 MB)
__device__ float g_hbuf[2][Bn * Hn];
__device__ float g_c[Bn * Hn];
__device__ float g_att[Bn * Hn];
__device__ float g_se[Bn * Hn];
__device__ float g_pm[NBLK], g_ps[NBLK];
__device__ float g_pctx[NBLK * Hn];
__device__ volatile unsigned g_gen;
__device__ unsigned g_cnt;

struct SA {                         // phase A (29.3 KB)
    float xs[32][132];              // x staging [b][k]
    float ws[8][132];               // weight rows staging [r][k]
    float part[8][8][32];           // split-k partials [warp][row][b]
};
struct SCc {                        // phase C (16.5 KB)
    float m[8], s[8];
    float ctx[8][Hn];
};
union __align__(16) SmemU {
    SA a;
    SCc c;
    float es[32][132];              // precompute enc staging
    float hb[Hn];                   // phase B h staging
};

DINL void gsync() {
    __threadfence();
    __syncthreads();
    if (threadIdx.x == 0) {
        unsigned target = g_gen + 1u;
        if (atomicAdd(&g_cnt, 1u) == gridDim.x - 1u) {
            g_cnt = 0u;
            __threadfence();
            g_gen = target;
        } else {
            while (g_gen != target) { __nanosleep(32); }
            __threadfence();
        }
    }
    __syncthreads();
}

DINL float wredsum(float v) {
    v += __shfl_xor_sync(0xffffffffu, v, 16);
    v += __shfl_xor_sync(0xffffffffu, v, 8);
    v += __shfl_xor_sync(0xffffffffu, v, 4);
    v += __shfl_xor_sync(0xffffffffu, v, 2);
    v += __shfl_xor_sync(0xffffffffu, v, 1);
    return v;
}

DINL float sigm(float x) { return 1.0f / (1.0f + __expf(-x)); }

DINL void ffma2(unsigned long long& acc, unsigned long long a, unsigned long long b) {
    asm("fma.rn.f32x2 %0, %1, %2, %0;" : "+l"(acc) : "l"(a), "l"(b));
}
// acc = acc * c1p + he * wvp   (packed f32x2)
DINL void ctxupd(unsigned long long& acc, unsigned long long c1p,
                 unsigned long long he, unsigned long long wvp) {
    unsigned long long t;
    asm("mul.rn.f32x2 %0, %1, %2;" : "=l"(t) : "l"(he), "l"(wvp));
    asm("fma.rn.f32x2 %0, %0, %1, %2;" : "+l"(acc) : "l"(c1p), "l"(t));
}
DINL unsigned long long packf2(float a, float b) {
    unsigned long long r;
    asm("mov.b64 %0, {%1, %2};" : "=l"(r) : "f"(a), "f"(b));
    return r;
}
DINL float lo2(unsigned long long v) { return __uint_as_float((unsigned)v); }
DINL float hi2(unsigned long long v) { return __uint_as_float((unsigned)(v >> 32)); }
DINL float red2(unsigned long long v) { return lo2(v) + hi2(v); }

__global__ void __launch_bounds__(NTHR, 2) aas_kernel(
    const float* __restrict__ y,    const float* __restrict__ enc,
    const float* __restrict__ W_ih, const float* __restrict__ b_ih,
    const float* __restrict__ W_hh, const float* __restrict__ b_hh,
    const float* __restrict__ W_s,  const float* __restrict__ b_s,
    const float* __restrict__ W_h,  const float* __restrict__ b_h,
    float* __restrict__ outp)
{
    __shared__ SmemU smu;
    __shared__ float sm_g[8][32];

    const int tid  = threadIdx.x;
    const int lane = tid & 31;
    const int w    = tid >> 5;
    const int bid  = blockIdx.x;
    const int gtid = bid * NTHR + tid;

    // ---------------- init state ----------------
    for (int i = gtid; i < Bn * Hn; i += NBLK * NTHR) {
        g_hbuf[0][i] = 0.f; g_hbuf[1][i] = 0.f; g_c[i] = 0.f;
        __stcg(&g_att[i], 0.f);
    }

    // ---------------- precompute h_e = enc @ W_h^T + b_h ----------------
    for (int rg = bid; rg < (Bn * Ln) / 32; rg += NBLK) {
        for (int sub = 0; sub < 4; sub++) {
            const int kb = w * 64 + sub * 16;
            unsigned long long acc[16];
#pragma unroll
            for (int kk = 0; kk < 16; kk++) acc[kk] = 0ull;
            for (int ch = 0; ch < 4; ch++) {
                __syncthreads();
#pragma unroll
                for (int rr = 0; rr < 4; rr++) {
                    const int bb = w * 4 + rr;
                    *(float4*)&smu.es[bb][lane * 4] =
                        *(const float4*)(enc + (rg * 32 + bb) * Hn + ch * 128 + lane * 4);
                }
                __syncthreads();
#pragma unroll 4
                for (int h4 = 0; h4 < 128; h4 += 4) {
                    const ulonglong2 xv = *(const ulonglong2*)&smu.es[lane][h4];
                    const float* wp = W_h + ch * 128 + h4;
#pragma unroll
                    for (int kk = 0; kk < 16; kk++) {
                        const ulonglong2 wv = *(const ulonglong2*)(wp + (kb + kk) * Hn);
                        ffma2(acc[kk], wv.x, xv.x);
                        ffma2(acc[kk], wv.y, xv.y);
                    }
                }
            }
            float* dst = g_he + (rg * 32 + lane) * Hn + kb;
#pragma unroll
            for (int kk = 0; kk < 16; kk++)
                dst[kk] = red2(acc[kk]) + b_h[kb + kk];
        }
    }
    gsync();

    // ==================== time-step loop ====================
#pragma unroll 1
    for (int ts = 0; ts < Sn; ts++) {
        const int cur = ts & 1, nxt = cur ^ 1;

        // ---------- A: gates GEMM, register-tiled split-K ----------
        // block owns 8 gate rows; warp w stages row w AND owns k-slice [w*16,+16) of each chunk
        {
            const int q = w & 3, j = w >> 2;
            const int r = q * Hn + bid * 2 + j;      // this warp's staging gate row
            unsigned long long acc2[8];
#pragma unroll
            for (int r8 = 0; r8 < 8; r8++) acc2[r8] = 0ull;

            float4 pf[4]; float4 pw;
            auto ldx = [&](int ch) {
#pragma unroll
                for (int rr = 0; rr < 4; rr++) {
                    const int bb = w * 4 + rr;
                    if (ch < 2)
                        pf[rr] = *(const float4*)(y + (bb * Sn + ts) * En + ch * 128 + lane * 4);
                    else if (ch < 6)
                        pf[rr] = __ldcg((const float4*)(g_att + bb * Hn + (ch - 2) * 128 + lane * 4));
                    else
                        pf[rr] = __ldcg((const float4*)(g_hbuf[cur] + bb * Hn + (ch - 6) * 128 + lane * 4));
                }
                const float* wp = (ch < 6) ? W_ih + r * 768 + ch * 128
                                           : W_hh + r * Hn + (ch - 6) * 128;
                pw = *(const float4*)(wp + lane * 4);
            };

            ldx(0);
#pragma unroll 1
            for (int ch = 0; ch < 10; ch++) {
                __syncthreads();
#pragma unroll
                for (int rr = 0; rr < 4; rr++)
                    *(float4*)&smu.a.xs[w * 4 + rr][lane * 4] = pf[rr];
                *(float4*)&smu.a.ws[w][lane * 4] = pw;
                __syncthreads();
                if (ch < 9) ldx(ch + 1);

                const int kb = w * 16;
#pragma unroll
                for (int t = 0; t < 4; t++) {
                    const ulonglong2 xv = *(const ulonglong2*)&smu.a.xs[lane][kb + t * 4];
#pragma unroll
                    for (int r8 = 0; r8 < 8; r8++) {
                        const ulonglong2 wv = *(const ulonglong2*)&smu.a.ws[r8][kb + t * 4];
                        ffma2(acc2[r8], wv.x, xv.x);
                        ffma2(acc2[r8], wv.y, xv.y);
                    }
                }
            }
#pragma unroll
            for (int r8 = 0; r8 < 8; r8++)
                smu.a.part[w][r8][lane] = red2(acc2[r8]);
            __syncthreads();
            {   // split-k reduce: thread (row=w, batch=lane)
                float tot = 0.f;
#pragma unroll
                for (int w2 = 0; w2 < 8; w2++) tot += smu.a.part[w2][w][lane];
                const int qq = w & 3, jj = w >> 2;
                const int grow = qq * Hn + bid * 2 + jj;
                sm_g[w][lane] = tot + b_ih[grow] + b_hh[grow];
            }
            __syncthreads();
            if (tid < 64) {
                const int bb = tid & 31, jj = tid >> 5, u = bid * 2 + jj;
                const float ig = sigm(sm_g[0 + jj * 4][bb]);
                const float fg = sigm(sm_g[1 + jj * 4][bb]);
                const float gg = tanhf(sm_g[2 + jj * 4][bb]);
                const float og = sigm(sm_g[3 + jj * 4][bb]);
                const float c = fmaf(fg, g_c[bb * Hn + u], ig * gg);
                g_c[bb * Hn + u] = c;
                const float h = og * tanhf(c);
                __stcg(&g_hbuf[nxt][bb * Hn + u], h);
                outp[(bb * Sn + ts) * Hn + u] = h;
            }
        }
        gsync();

        // ---------- B: partitioned s_e = W_s h + b_s (64 outputs/block) ----------
        {
            const int b = bid >> 3, mb = (bid & 7) * 64;
            if (tid < 128)
                *(float4*)&smu.hb[tid * 4] =
                    __ldcg((const float4*)(g_hbuf[nxt] + b * Hn + tid * 4));
            __syncthreads();
#pragma unroll
            for (int rp = 0; rp < 4; rp++) {
                const int m0 = mb + w * 8 + rp * 2;
                unsigned long long a0 = 0ull, a1 = 0ull;
#pragma unroll
                for (int c = 0; c < 4; c++) {
                    const ulonglong2 xv = *(const ulonglong2*)&smu.hb[c * 128 + lane * 4];
                    const ulonglong2 w0 = *(const ulonglong2*)(W_s + m0 * Hn + c * 128 + lane * 4);
                    const ulonglong2 w1 = *(const ulonglong2*)(W_s + (m0 + 1) * Hn + c * 128 + lane * 4);
                    ffma2(a0, w0.x, xv.x); ffma2(a0, w0.y, xv.y);
                    ffma2(a1, w1.x, xv.x); ffma2(a1, w1.y, xv.y);
                }
                float e0 = wredsum(red2(a0));
                float e1 = wredsum(red2(a1));
                if (lane == 0) {
                    __stcg(&g_se[b * Hn + m0],     e0 + b_s[m0]);
                    __stcg(&g_se[b * Hn + m0 + 1], e1 + b_s[m0 + 1]);
                }
            }
        }
        gsync();

        // ---------- C: single-pass branchless online-softmax attention ----------
        {
            const int b = bid >> 3, chunk = bid & 7;

            unsigned long long se_[8];
#pragma unroll
            for (int jj = 0; jj < 4; jj++) {
                const ulonglong2 t =
                    __ldcg((const ulonglong2*)(g_se + b * Hn + jj * 128 + lane * 4));
                se_[2 * jj] = t.x; se_[2 * jj + 1] = t.y;
            }
            unsigned long long ctx2[8];
#pragma unroll
            for (int jj = 0; jj < 8; jj++) ctx2[jj] = 0ull;
            float m = -1e30f, s = 0.f;

            const float* hbase = g_he + (b * Ln + chunk * CROWS + w * 16) * Hn + lane * 4;
#pragma unroll 2
            for (int li = 0; li < 16; li++) {
                const float* hp = hbase + li * Hn;
                const ulonglong2 u0 = *(const ulonglong2*)(hp);
                const ulonglong2 u1 = *(const ulonglong2*)(hp + 128);
                const ulonglong2 u2 = *(const ulonglong2*)(hp + 256);
                const ulonglong2 u3 = *(const ulonglong2*)(hp + 384);
                unsigned long long ea = 0ull, eb = 0ull;
                ffma2(ea, u0.x, se_[0]); ffma2(eb, u0.y, se_[1]);
                ffma2(ea, u1.x, se_[2]); ffma2(eb, u1.y, se_[3]);
                ffma2(ea, u2.x, se_[4]); ffma2(eb, u2.y, se_[5]);
                ffma2(ea, u3.x, se_[6]); ffma2(eb, u3.y, se_[7]);
                const float e = wredsum(red2(ea) + red2(eb));

                const float nm = fmaxf(m, e);
                const float c1 = __expf(m - nm);
                const float wv = __expf(e - nm);
                s = fmaf(s, c1, wv);
                m = nm;
                const unsigned long long c1p = packf2(c1, c1);
                const unsigned long long wvp = packf2(wv, wv);
                ctxupd(ctx2[0], c1p, u0.x, wvp); ctxupd(ctx2[1], c1p, u0.y, wvp);
                ctxupd(ctx2[2], c1p, u1.x, wvp); ctxupd(ctx2[3], c1p, u1.y, wvp);
                ctxupd(ctx2[4], c1p, u2.x, wvp); ctxupd(ctx2[5], c1p, u2.y, wvp);
                ctxupd(ctx2[6], c1p, u3.x, wvp); ctxupd(ctx2[7], c1p, u3.y, wvp);
            }
            if (lane == 0) { smu.c.m[w] = m; smu.c.s[w] = s; }
#pragma unroll
            for (int jj = 0; jj < 4; jj++) {
                ulonglong2 st;
                st.x = ctx2[2 * jj]; st.y = ctx2[2 * jj + 1];
                *(ulonglong2*)&smu.c.ctx[w][jj * 128 + lane * 4] = st;
            }
            __syncthreads();
            {
                float M = smu.c.m[0];
#pragma unroll
                for (int w2 = 1; w2 < 8; w2++) M = fmaxf(M, smu.c.m[w2]);
                float wsc[8]; float Sb = 0.f;
#pragma unroll
                for (int w2 = 0; w2 < 8; w2++) {
                    wsc[w2] = __expf(smu.c.m[w2] - M);
                    Sb = fmaf(wsc[w2], smu.c.s[w2], Sb);
                }
#pragma unroll
                for (int rr = 0; rr < 2; rr++) {
                    const int h = tid + rr * 256;
                    float v = 0.f;
#pragma unroll
                    for (int w2 = 0; w2 < 8; w2++)
                        v = fmaf(wsc[w2], smu.c.ctx[w2][h], v);
                    __stcg(&g_pctx[bid * Hn + h], v);
                }
                if (tid == 0) { __stcg(&g_pm[bid], M); __stcg(&g_ps[bid], Sb); }
            }
        }
        gsync();

        // ---------- D: combine 8 chunk-partials -> att ----------
        if (gtid < Bn * Hn) {
            const int b = gtid >> 9, h = gtid & 511;
            float pm[8];
#pragma unroll
            for (int cc = 0; cc < 8; cc++) pm[cc] = __ldcg(&g_pm[b * 8 + cc]);
            float M = pm[0];
#pragma unroll
            for (int cc = 1; cc < 8; cc++) M = fmaxf(M, pm[cc]);
            float Sd = 0.f, v = 0.f;
#pragma unroll
            for (int cc = 0; cc < 8; cc++) {
                const float wsc = __expf(pm[cc] - M);
                Sd = fmaf(wsc, __ldcg(&g_ps[b * 8 + cc]), Sd);
                v  = fmaf(wsc, __ldcg(&g_pctx[(b * 8 + cc) * Hn + h]), v);
            }
            const float a = v / Sd;
            __stcg(&g_att[b * Hn + h], a);
            outp[Bn * Sn * Hn + (b * Sn + ts) * Hn + h] = a;
        }
        gsync();
    }
}

extern "C" void kernel_launch(void* const* d_in, const int* in_sizes, int n_in,
                              void* d_out, int out_size) {
    (void)in_sizes; (void)n_in; (void)out_size;
    aas_kernel<<<NBLK, NTHR>>>(
        (const float*)d_in[0], (const float*)d_in[1],
        (const float*)d_in[2], (const float*)d_in[3],
        (const float*)d_in[4], (const float*)d_in[5],
        (const float*)d_in[6], (const float*)d_in[7],
        (const float*)d_in[8], (const float*)d_in[9],
        (float*)d_out);
}